// round 17
// baseline (speedup 1.0000x reference)
#include <cuda_runtime.h>

#define G_TOTAL 32768
#define H1      150
#define PP      8

using u64 = unsigned long long;
using u32 = unsigned int;

// ---- bf16 / tf32 / mma helpers ------------------------------------------------
__device__ __forceinline__ u32 cvtbf2(float hi, float lo) {
    u32 d;
    asm("cvt.rn.bf16x2.f32 %0,%1,%2;" : "=r"(d) : "f"(hi), "f"(lo));
    return d;
}
__device__ __forceinline__ u32 tf32r(float f) {
    u32 u;
    asm("cvt.rna.tf32.f32 %0,%1;" : "=r"(u) : "f"(f));
    return u;
}
__device__ __forceinline__ void mma16816(float& d0, float& d1, float& d2, float& d3,
                                         u32 a0, u32 a1, u32 a2, u32 a3,
                                         u32 b0, u32 b1,
                                         float c0, float c1, float c2, float c3)
{
    asm volatile("mma.sync.aligned.m16n8k16.row.col.f32.bf16.bf16.f32 "
                 "{%0,%1,%2,%3},{%4,%5,%6,%7},{%8,%9},{%10,%11,%12,%13};"
                 : "=f"(d0), "=f"(d1), "=f"(d2), "=f"(d3)
                 : "r"(a0), "r"(a1), "r"(a2), "r"(a3), "r"(b0), "r"(b1),
                   "f"(c0), "f"(c1), "f"(c2), "f"(c3));
}
__device__ __forceinline__ void mmatf32(float& d0, float& d1, float& d2, float& d3,
                                        u32 a0, u32 a1, u32 a2, u32 a3,
                                        u32 b0, u32 b1,
                                        float c0, float c1, float c2, float c3)
{
    asm volatile("mma.sync.aligned.m16n8k8.row.col.f32.tf32.tf32.f32 "
                 "{%0,%1,%2,%3},{%4,%5,%6,%7},{%8,%9},{%10,%11,%12,%13};"
                 : "=f"(d0), "=f"(d1), "=f"(d2), "=f"(d3)
                 : "r"(a0), "r"(a1), "r"(a2), "r"(a3), "r"(b0), "r"(b1),
                   "f"(c0), "f"(c1), "f"(c2), "f"(c3));
}

// ---- shared-memory layout (float offsets) ------------------------------------
// Biases folded: k=18 of input = 1.0 (W1 row 18 = b1); j=150 hidden = 1
// (W2 row 150 = b2); agg slot k=40 = 1.0 (W3T row 40 = b3).
// W1T : [160 j][24 k] bf16 (12 u32/row)               1920
// W2T : [8 p][160 j] bf16                              640
// W4s : [152] f32                                      152
// W3T : [152 n][52 k] tf32 (48 used, pad->52)          7904
// AGG : [32 g][52 k] tf32 (40 stats + 1.0 + pad)       1664
// inb : 8 warps x 1536 floats (128 rows x 48B bf16)    12288
//       overlays: per-warp aw = 4 groups x (32x32B + 32B pad)
//                 block-wide zB[32 g][164] f32 (after stats barrier)
#define SM_W1T 0
#define SM_W2T 1920
#define SM_W4  2560
#define SM_W3T 2712
#define SM_AGG 10616
#define SM_INB 12280
#define SM_FLOATS (12280 + 12288)
#define SM_BYTES  (SM_FLOATS * 4)

#define AW_GSTRIDE 1056   // bytes per group slice in aw (32*32 + 32 pad)
#define ZB_STRIDE  164    // floats per group row in zB

__global__ void __launch_bounds__(256, 2)
minn_fused_mma6_kernel(const float* __restrict__ x,
                       const int*   __restrict__ kmer,
                       const int*   __restrict__ indices,
                       const float* __restrict__ emb,
                       const float* __restrict__ W1, const float* __restrict__ b1,
                       const float* __restrict__ W2, const float* __restrict__ b2,
                       const float* __restrict__ W3, const float* __restrict__ b3,
                       const float* __restrict__ W4, const float* __restrict__ b4,
                       float* __restrict__ out)
{
    extern __shared__ float sm[];
    u32*   W1T  = (u32*)(sm + SM_W1T);
    u32*   W2T  = (u32*)(sm + SM_W2T);
    float* W4s  = sm + SM_W4;
    u32*   W3Ts = (u32*)(sm + SM_W3T);
    u32*   aggB = (u32*)(sm + SM_AGG);
    float* zB   = sm + SM_INB;            // overlay (valid after stats barrier)

    const int tid = threadIdx.x;

    // ---- stage weight tables (block-cooperative, 256 threads) ----
    for (int i = tid; i < 160 * 12; i += 256) {
        int j = i / 12, kp = i - j * 12;
        int k0 = 2 * kp, k1 = 2 * kp + 1;
        float w0 = 0.0f, w1 = 0.0f;
        if (k0 < 18)        w0 = (j < H1) ? W1[k0 * H1 + j] : 0.0f;
        else if (k0 == 18)  w0 = (j < H1) ? b1[j] : (j == H1 ? 1.0f : 0.0f);
        if (k1 < 18)        w1 = (j < H1) ? W1[k1 * H1 + j] : 0.0f;
        else if (k1 == 18)  w1 = (j < H1) ? b1[j] : (j == H1 ? 1.0f : 0.0f);
        W1T[i] = cvtbf2(w1, w0);
    }
    for (int i = tid; i < 8 * 80; i += 256) {
        int p = i / 80, jp = i - p * 80;
        int j0 = 2 * jp, j1 = j0 + 1;
        float w0 = (j0 < H1) ? W2[j0 * PP + p] : (j0 == H1 ? b2[p] : 0.0f);
        float w1 = (j1 < H1) ? W2[j1 * PP + p] : (j1 == H1 ? b2[p] : 0.0f);
        W2T[i] = cvtbf2(w1, w0);
    }
    // W3T[n][k] (tf32): k<40 = W3[k][n]; k==40 = b3[n]; else 0
    for (int i = tid; i < 152 * 48; i += 256) {
        int n = i / 48, k = i - n * 48;
        float v = 0.0f;
        if (n < H1) {
            if (k < 40)       v = W3[k * H1 + n];
            else if (k == 40) v = b3[n];
        }
        W3Ts[n * 52 + k] = tf32r(v);
    }
    // AGG bias slots (k=40..51): 1.0 at k=40, 0 elsewhere
    for (int i = tid; i < 32 * 12; i += 256) {
        int g = i / 12, k = 40 + (i - g * 12);
        aggB[g * 52 + k] = (k == 40) ? tf32r(1.0f) : 0u;
    }
    for (int i = tid; i < 152; i += 256)
        W4s[i] = (i < H1) ? W4[i] : 0.0f;
    const float b4v = __ldg(b4);
    __syncthreads();

    const int warp = tid >> 5;                     // 0..7
    const int lane = tid & 31;
    const int g0 = (blockIdx.x * 8 + warp) * 4;    // 4 groups per warp
    const int lq = lane >> 2;                      // fragment row (0..7)
    const int lc = lane & 3;                       // fragment col (0..3)

    char* inbw = (char*)(sm + SM_INB) + warp * 6144;   // 128 rows x 48 B bf16
    char* aw   = inbw;                                 // overlay

    // ---- stage this warp's 128 reads as 48B bf16 rows (conflict-free) ----
    const u32 ONE18 = cvtbf2(0.0f, 1.0f);
    #pragma unroll
    for (int i = 0; i < 4; ++i) {
        const int rr = i * 32 + lane;
        const int r = indices[(g0 + i) * 32 + lane];
        const float4* px = (const float4*)(x + (size_t)r * 16);
        float4 v0 = px[0], v1 = px[1], v2 = px[2], v3 = px[3];
        float2 e = ((const float2*)emb)[kmer[r]];
        uint4* dst = (uint4*)(inbw + rr * 48);
        dst[0] = make_uint4(cvtbf2(v0.y, v0.x), cvtbf2(v0.w, v0.z),
                            cvtbf2(v1.y, v1.x), cvtbf2(v1.w, v1.z));
        dst[1] = make_uint4(cvtbf2(v2.y, v2.x), cvtbf2(v2.w, v2.z),
                            cvtbf2(v3.y, v3.x), cvtbf2(v3.w, v3.z));
        dst[2] = make_uint4(cvtbf2(e.y, e.x), ONE18, 0u, 0u);
    }
    __syncwarp();

    // ---- two passes of 64 reads: GEMM1 (relu) chained into GEMM2 ----
    #pragma unroll 1
    for (int pass = 0; pass < 2; ++pass) {
        u32 Af[4][6];
        #pragma unroll
        for (int m = 0; m < 4; ++m) {
            const char* base = inbw + (pass * 64 + m * 16 + lq) * 48 + lc * 4;
            Af[m][0] = *(const u32*)(base);
            Af[m][1] = *(const u32*)(base + 8 * 48);
            Af[m][2] = *(const u32*)(base + 16);
            Af[m][3] = *(const u32*)(base + 8 * 48 + 16);
            Af[m][4] = *(const u32*)(base + 32);
            Af[m][5] = *(const u32*)(base + 8 * 48 + 32);
        }

        float C2[4][4];
        #pragma unroll
        for (int m = 0; m < 4; ++m)
            C2[m][0] = C2[m][1] = C2[m][2] = C2[m][3] = 0.0f;

        u32 a2f[4][4];

        #pragma unroll 2
        for (int t = 0; t < 10; ++t) {
            #pragma unroll
            for (int half = 0; half < 2; ++half) {
                const int n = 2 * t + half;
                const int j = 8 * n + lq;
                const char* wb = (const char*)W1T + j * 48 + lc * 4;
                u32 b00 = *(const u32*)(wb);
                u32 b01 = *(const u32*)(wb + 16);
                u32 b10 = *(const u32*)(wb + 32);
                #pragma unroll
                for (int m = 0; m < 4; ++m) {
                    float c0, c1, c2, c3;
                    mma16816(c0, c1, c2, c3,
                             Af[m][0], Af[m][1], Af[m][2], Af[m][3],
                             b00, b01, 0.0f, 0.0f, 0.0f, 0.0f);
                    mma16816(c0, c1, c2, c3,
                             Af[m][4], Af[m][5], 0u, 0u,
                             b10, 0u, c0, c1, c2, c3);
                    float h0 = fmaxf(c0, 0.0f);
                    float h1 = fmaxf(c1, 0.0f);
                    float h2 = fmaxf(c2, 0.0f);
                    float h3 = fmaxf(c3, 0.0f);
                    a2f[m][2 * half]     = cvtbf2(h1, h0);
                    a2f[m][2 * half + 1] = cvtbf2(h3, h2);
                }
            }
            {
                const char* w2b = (const char*)W2T + lq * 320 + (16 * t + 2 * lc) * 2;
                u32 w20 = *(const u32*)(w2b);
                u32 w21 = *(const u32*)(w2b + 16);
                #pragma unroll
                for (int m = 0; m < 4; ++m) {
                    mma16816(C2[m][0], C2[m][1], C2[m][2], C2[m][3],
                             a2f[m][0], a2f[m][1], a2f[m][2], a2f[m][3],
                             w20, w21,
                             C2[m][0], C2[m][1], C2[m][2], C2[m][3]);
                }
            }
        }

        // a = relu(C2) -> aw[group][row][p]
        #pragma unroll
        for (int m = 0; m < 4; ++m) {
            int rb = pass * 64 + m * 16 + lq;
            char* rowlo = aw + (rb >> 5) * AW_GSTRIDE + (rb & 31) * 32;
            int rb2 = rb + 8;
            char* rowhi = aw + (rb2 >> 5) * AW_GSTRIDE + (rb2 & 31) * 32;
            float2 lo = make_float2(fmaxf(C2[m][0], 0.0f),
                                    fmaxf(C2[m][1], 0.0f));
            float2 hi = make_float2(fmaxf(C2[m][2], 0.0f),
                                    fmaxf(C2[m][3], 0.0f));
            *(float2*)(rowlo + lc * 8) = lo;
            *(float2*)(rowhi + lc * 8) = hi;
        }
    }
    __syncwarp();

    // ---- per-(group,feature) stats in registers: thread = (g, p) ----
    {
        const int sg = lane >> 3;      // group within warp (0..3)
        const int sp = lane & 7;       // feature (0..7)
        const char* colp = aw + sg * AW_GSTRIDE + sp * 4;

        float v[32];
        float sum = 0.0f;
        #pragma unroll
        for (int i = 0; i < 32; ++i) {
            v[i] = *(const float*)(colp + i * 32);
            sum += v[i];
        }
        float mean = sum * (1.0f / 32.0f);
        float qacc = 0.0f;
        #pragma unroll
        for (int i = 0; i < 32; ++i) {
            float d = v[i] - mean;
            qacc = fmaf(d, d, qacc);
        }
        float var = qacc * (1.0f / 31.0f);

        // in-register bitonic sort (ascending), fully unrolled
        #pragma unroll
        for (int k = 2; k <= 32; k <<= 1) {
            #pragma unroll
            for (int j = k >> 1; j > 0; j >>= 1) {
                #pragma unroll
                for (int i = 0; i < 32; ++i) {
                    int l = i ^ j;
                    if (l > i) {
                        bool up = ((i & k) == 0);
                        float lo = fminf(v[i], v[l]);
                        float hi = fmaxf(v[i], v[l]);
                        v[i] = up ? lo : hi;
                        v[l] = up ? hi : lo;
                    }
                }
            }
        }

        // aggB[g][stat*8 + p] (tf32), block-level group id
        u32* aggw = aggB + (warp * 4 + sg) * 52 + sp;
        aggw[0]  = tf32r(mean);
        aggw[8]  = tf32r(var);
        aggw[16] = tf32r(v[0]);
        aggw[24] = tf32r(v[15]);
        aggw[32] = tf32r(v[31]);
    }
    __syncthreads();   // all stats visible; inb/aw dead -> zB overlay valid

    // ---- block-level tail GEMM: z[32 g][152 n] = relu(AGG[32][48] @ W3T^T) ----
    // 38 (mt,nt) tiles over 8 warps; tf32 m16n8k8, 6 k-steps
    #pragma unroll 1
    for (int s = warp; s < 38; s += 8) {
        const int mt = s & 1, nt = s >> 1;
        float d0 = 0.0f, d1 = 0.0f, d2 = 0.0f, d3 = 0.0f;
        const u32* arow0 = aggB + (mt * 16 + lq) * 52 + lc;
        const u32* arow1 = arow0 + 8 * 52;
        const u32* brow  = W3Ts + (nt * 8 + lq) * 52 + lc;
        #pragma unroll
        for (int ks = 0; ks < 6; ++ks) {
            u32 a0 = arow0[ks * 8];
            u32 a1 = arow1[ks * 8];
            u32 a2 = arow0[ks * 8 + 4];
            u32 a3 = arow1[ks * 8 + 4];
            u32 bb0 = brow[ks * 8];
            u32 bb1 = brow[ks * 8 + 4];
            mmatf32(d0, d1, d2, d3, a0, a1, a2, a3, bb0, bb1, d0, d1, d2, d3);
        }
        float* zlo = zB + (mt * 16 + lq) * ZB_STRIDE + nt * 8 + 2 * lc;
        float* zhi = zlo + 8 * ZB_STRIDE;
        *(float2*)zlo = make_float2(fmaxf(d0, 0.0f), fmaxf(d1, 0.0f));
        *(float2*)zhi = make_float2(fmaxf(d2, 0.0f), fmaxf(d3, 0.0f));
    }
    __syncthreads();

    // ---- final dot: out[g] = sigmoid(z[g] . W4 + b4), thread = (g, c) ----
    {
        const int g = tid >> 3;        // block group (0..31)
        const int c = tid & 7;         // chunk (0..7), 19 j's each (8*19=152)
        const float* zr = zB + g * ZB_STRIDE + c * 19;
        const float* wr = W4s + c * 19;
        float acc = 0.0f;
        #pragma unroll
        for (int i = 0; i < 19; ++i)
            acc = fmaf(zr[i], wr[i], acc);
        acc += __shfl_xor_sync(0xffffffffu, acc, 1);
        acc += __shfl_xor_sync(0xffffffffu, acc, 2);
        acc += __shfl_xor_sync(0xffffffffu, acc, 4);
        if (c == 0)
            out[blockIdx.x * 32 + g] = 1.0f / (1.0f + __expf(-(acc + b4v)));
    }
}

extern "C" void kernel_launch(void* const* d_in, const int* in_sizes, int n_in,
                              void* d_out, int out_size)
{
    const float* x       = (const float*)d_in[0];
    const int*   kmer    = (const int*)  d_in[1];
    const int*   indices = (const int*)  d_in[2];
    const float* emb     = (const float*)d_in[3];
    const float* W1      = (const float*)d_in[4];
    const float* b1      = (const float*)d_in[5];
    const float* W2      = (const float*)d_in[6];
    const float* b2      = (const float*)d_in[7];
    const float* W3      = (const float*)d_in[8];
    const float* b3      = (const float*)d_in[9];
    const float* W4      = (const float*)d_in[10];
    const float* b4      = (const float*)d_in[11];
    float* out = (float*)d_out;

    cudaFuncSetAttribute(minn_fused_mma6_kernel,
                         cudaFuncAttributeMaxDynamicSharedMemorySize, SM_BYTES);

    // 8 warps/block * 4 groups/warp = 32 groups per block
    const int blocks = G_TOTAL / 32;   // 1024
    minn_fused_mma6_kernel<<<blocks, 256, SM_BYTES>>>(
        x, kmer, indices, emb, W1, b1, W2, b2, W3, b3, W4, b4, out);
}